// round 12
// baseline (speedup 1.0000x reference)
#include <cuda_runtime.h>
#define NSTEP 255

__device__ float g_wz[8 * 128 * 128];
__device__ float g_M[7 * 128 * 64];
__device__ float g_F0[128 * 64];
__device__ float g_cond[NSTEP * 2 * 1024];
__device__ float g_ds1[2 * 64 * 512];
__device__ float g_ds2[2 * 64 * 256];
__device__ float g_outpre[2 * 64 * 256];
__device__ float g_up1[2 * 64 * 512];

__device__ __forceinline__ float dot4(float4 a, float4 x) {
    return a.x * x.x + a.y * x.y + a.z * x.z + a.w * x.w;
}
__device__ __forceinline__ float4 relu4(float4 v) {
    v.x = fmaxf(v.x, 0.f); v.y = fmaxf(v.y, 0.f);
    v.z = fmaxf(v.z, 0.f); v.w = fmaxf(v.w, 0.f);
    return v;
}
__device__ __forceinline__ float gatefn(float z0, float z1) {
    float e0 = __expf(2.f * z0), e1 = __expf(-z1);
    return (1.f - __fdividef(2.f, e0 + 1.f)) * __fdividef(1.f, 1.f + e1);
}
#define BARS(id, n) asm volatile("bar.sync %0,%1;" ::"r"(id), "r"(n) : "memory")
#define BARA(id, n) asm volatile("bar.arrive %0,%1;" ::"r"(id), "r"(n) : "memory")

__global__ void k_downbn(int sel, const float* __restrict__ w,
                         const float* __restrict__ song,
                         const float* __restrict__ gamma,
                         const float* __restrict__ beta) {
    int o = blockIdx.x, tid = threadIdx.x;
    int Lout = sel ? 256 : 512;
    const float* in = sel ? g_ds1 : song;
    float* out = sel ? g_ds2 : g_ds1;
    __shared__ float wr[128], rs[256], rq[256];
    if (tid < 128) wr[tid] = w[o * 128 + tid];
    __syncthreads();
    float vals[4];
    int cnt = 2 * Lout / 256;
    float s = 0.f, q = 0.f;
    for (int j = 0; j < cnt; j++) {
        int i = tid + j * 256, bb = i >= Lout, l = i - bb * Lout;
        const float* xin = in + bb * 64 * 2 * Lout;
        float acc = 0.f;
#pragma unroll
        for (int c = 0; c < 64; c++)
            acc += wr[2 * c] * xin[c * 2 * Lout + 2 * l]
                 + wr[2 * c + 1] * xin[c * 2 * Lout + 2 * l + 1];
        vals[j] = acc; s += acc; q += acc * acc;
    }
    rs[tid] = s; rq[tid] = q; __syncthreads();
    for (int st = 128; st; st >>= 1) {
        if (tid < st) { rs[tid] += rs[tid + st]; rq[tid] += rq[tid + st]; }
        __syncthreads();
    }
    float m = rs[0] / (2.f * Lout);
    float inv = rsqrtf(rq[0] / (2.f * Lout) - m * m + 1e-5f);
    float ga = gamma[o], be = beta[o];
    for (int j = 0; j < cnt; j++) {
        int i = tid + j * 256, bb = i >= Lout, l = i - bb * Lout;
        out[(bb * 64 + o) * Lout + l] = fmaxf(ga * (vals[j] - m) * inv + be, 0.f);
    }
}

__global__ void k_upbn(int sel, const float* __restrict__ w,
                       const float* __restrict__ gamma,
                       const float* __restrict__ beta, float* __restrict__ hout) {
    int o = blockIdx.x, tid = threadIdx.x;
    int Lin = sel ? 512 : 256;
    const float* in = sel ? g_up1 : g_outpre;
    float* out = sel ? hout : g_up1;
    __shared__ float wr[128], rs[256], rq[256];
    if (tid < 128) { int i = tid >> 1, k = tid & 1; wr[tid] = w[(i * 64 + o) * 2 + k]; }
    __syncthreads();
    int cnt = 2 * Lin / 256;
    float v0[4], v1[4];
    float s = 0.f, q = 0.f;
    for (int j = 0; j < cnt; j++) {
        int i = tid + j * 256, bb = i >= Lin, l = i - bb * Lin;
        float a0 = 0.f, a1 = 0.f;
#pragma unroll
        for (int c = 0; c < 64; c++) {
            float x = in[(bb * 64 + c) * Lin + l];
            a0 += wr[2 * c] * x; a1 += wr[2 * c + 1] * x;
        }
        v0[j] = a0; v1[j] = a1;
        s += a0 + a1; q += a0 * a0 + a1 * a1;
    }
    rs[tid] = s; rq[tid] = q; __syncthreads();
    for (int st = 128; st; st >>= 1) {
        if (tid < st) { rs[tid] += rs[tid + st]; rq[tid] += rq[tid + st]; }
        __syncthreads();
    }
    float m = rs[0] / (4.f * Lin);
    float inv = rsqrtf(rq[0] / (4.f * Lin) - m * m + 1e-5f);
    float ga = gamma[o], be = beta[o];
    for (int j = 0; j < cnt; j++) {
        int i = tid + j * 256, bb = i >= Lin, l = i - bb * Lin;
        float* op = out + (bb * 64 + o) * 2 * Lin + 2 * l;
        op[0] = fmaxf(ga * (v0[j] - m) * inv + be, 0.f);
        op[1] = fmaxf(ga * (v1[j] - m) * inv + be, 0.f);
    }
}

// prep: cond GEMM (0-127), wz transpose (128-639), zero (640),
//       M = Wzc_{l+1}*Wres_l (641-864), F0 = Wzc_0*Wembed (865-896)
__global__ void k_prep(const float* __restrict__ wdil,
                       const float* __restrict__ wcond,
                       const float* __restrict__ wres,
                       const float* __restrict__ wembed) {
    int bx = blockIdx.x, tid = threadIdx.x;
    if (bx >= 865) {
        int idx = (bx - 865) * 256 + tid;
        int i = idx >> 6, k = idx & 63;
        float acc = 0.f;
        for (int r = 0; r < 64; r++)
            acc += wdil[i * 128 + 2 * r + 1] * wembed[r * 64 + k];
        g_F0[idx] = acc;
        return;
    }
    if (bx >= 641) {
        int idx = (bx - 641) * 256 + tid;
        int l = idx >> 13, i = (idx >> 6) & 127, k = idx & 63;
        float acc = 0.f;
        for (int r = 0; r < 64; r++)
            acc += wdil[(((l + 1) * 128 + i) * 64 + r) * 2 + 1]
                 * wres[l * 4096 + r * 64 + k];
        g_M[idx] = acc;
        return;
    }
    if (bx >= 640) {
        if (tid < 128) g_outpre[tid * 256] = 0.f;
        return;
    }
    if (bx >= 128) {
        int idx = (bx - 128) * 256 + tid;
        int r = idx & 63, t = (idx >> 6) & 1, o = (idx >> 7) & 127, l = idx >> 14;
        g_wz[idx] = wdil[((l * 128 + o) * 64 + r) * 2 + t];
        return;
    }
    __shared__ __align__(16) float wt[128 * 64];
    __shared__ __align__(16) float col[128];
    int ob = (bx & 7) * 128, gy = bx >> 3;
    for (int i = tid; i < 128 * 64; i += 256) wt[i] = wcond[ob * 64 + i];
    for (int nn = 0; nn < 16; nn++) {
        int n = gy * 16 + nn;
        if (n >= NSTEP) break;
        __syncthreads();
        if (tid < 128) {
            int b = tid >> 6, c = tid & 63;
            col[tid] = g_ds2[(b * 64 + c) * 256 + n];
        }
        __syncthreads();
        int oo = tid >> 1, b = tid & 1;
        const float4* w4 = (const float4*)(wt + oo * 64);
        const float4* c4 = (const float4*)(col + b * 64);
        float acc = 0.f;
#pragma unroll
        for (int j = 0; j < 16; j++) acc += dot4(w4[j], c4[j]);
        g_cond[(n * 2 + b) * 1024 + ob + oo] = acc;
    }
}

#define S_RING 0
#define S_SC   16320
#define S_GVB  18368
#define S_XB   18880
#define S_PB   19392
#define S_R0   20416
#define S_SKIP 20672
#define S_H2   20928
#define S_YV   21184
#define S_TOT  21248

__constant__ int c_dil[8]  = {1, 2, 4, 8, 16, 32, 64, 128};
__constant__ int c_roff[8] = {0, 1, 3, 7, 15, 31, 63, 127};

__global__ void __launch_bounds__(1024, 1)
k_loop(const float* __restrict__ wembed, const float* __restrict__ wres,
       const float* __restrict__ wskip, const float* __restrict__ wout,
       const float* __restrict__ wend) {
    extern __shared__ float sm[];
    float* ring  = sm + S_RING;
    float* sc    = sm + S_SC;
    float* gvb   = sm + S_GVB;
    float* xb    = sm + S_XB;
    float* Pb    = sm + S_PB;
    float* R0b   = sm + S_R0;
    float* skipv = sm + S_SKIP;
    float* h2    = sm + S_H2;
    float* yv    = sm + S_YV;
    const int b = blockIdx.x, tid = threadIdx.x;

    for (int i = tid; i < 16320; i += 1024) ring[i] = 0.f;
    sc[tid] = g_cond[b * 1024 + tid];
    if (tid < 64) yv[tid] = 0.f;
    __syncthreads();

    if (tid < 512) {
        // ===== group A: serial chain z_l = M_{l-1} g_{l-1} + P_l + c_l =====
        const int o = tid >> 3, p = tid & 7;
        const int mi0 = o * 16 + p * 2, mi1 = (64 + o) * 16 + p * 2;
        float4 ML0, ML1, ML2, ML3;
        {
            const float4* m4 = (const float4*)g_M;
            ML0 = m4[mi0]; ML1 = m4[mi0 + 1]; ML2 = m4[mi1]; ML3 = m4[mi1 + 1];
            if (p == 0) gvb[o] = gatefn(sc[o], sc[64 + o]);   // g_0(0)
            BARS(5, 512); BARA(10, 1024);                     // g_0 ready (even)
        }
        for (int n = 0; n < NSTEP; n++) {
            const float* scur = sc + (n & 1) * 1024;
            const float* snxt = sc + ((n + 1) & 1) * 1024;
#pragma unroll
            for (int l = 1; l < 8; l++) {
                const float4* g4 = (const float4*)(gvb + (l - 1) * 64) + p * 2;
                float4 x0 = g4[0], x1 = g4[1];
                float a0 = dot4(ML0, x0) + dot4(ML1, x1);
                float a1 = dot4(ML2, x0) + dot4(ML3, x1);
                const float4* m4 = (l < 7) ? (const float4*)g_M + l * 2048
                                           : (const float4*)g_F0;
                ML0 = m4[mi0]; ML1 = m4[mi0 + 1]; ML2 = m4[mi1]; ML3 = m4[mi1 + 1];
                a0 += __shfl_xor_sync(~0u, a0, 1); a1 += __shfl_xor_sync(~0u, a1, 1);
                a0 += __shfl_xor_sync(~0u, a0, 2); a1 += __shfl_xor_sync(~0u, a1, 2);
                a0 += __shfl_xor_sync(~0u, a0, 4); a1 += __shfl_xor_sync(~0u, a1, 4);
                BARS(8 + (l & 1), 1024);              // P_l ready
                if (p == 0) {
                    float z0 = a0 + Pb[l * 128 + o]      + scur[l * 128 + o];
                    float z1 = a1 + Pb[l * 128 + 64 + o] + scur[l * 128 + 64 + o];
                    gvb[l * 64 + o] = gatefn(z0, z1);
                }
                BARS(5, 512); BARA(10 + (l & 1), 1024);   // g_l ready (parity)
            }
            BARS(3, 1024);                            // skipv ready
            {   // h2 = relu(wout @ relu(skipv))
                int o2 = tid >> 1, q = tid & 1;
                const float4* w4 = (const float4*)wout + o2 * 64 + q * 32;
                const float4* v4 = (const float4*)skipv + q * 32;
                float c0 = 0.f, c1 = 0.f, c2 = 0.f, c3 = 0.f;
#pragma unroll
                for (int j = 0; j < 8; j++) {
                    c0 += dot4(w4[4 * j],     relu4(v4[4 * j]));
                    c1 += dot4(w4[4 * j + 1], relu4(v4[4 * j + 1]));
                    c2 += dot4(w4[4 * j + 2], relu4(v4[4 * j + 2]));
                    c3 += dot4(w4[4 * j + 3], relu4(v4[4 * j + 3]));
                }
                float acc = (c0 + c1) + (c2 + c3);
                acc += __shfl_xor_sync(~0u, acc, 1);
                if (q == 0) h2[o2] = fmaxf(acc, 0.f);
            }
            BARS(4, 512);
            {   // y = wend @ h2
                const float4* w4 = (const float4*)wend + o * 64 + p * 8;
                const float4* h4 = (const float4*)h2 + p * 8;
                float y0 = dot4(w4[0], h4[0]) + dot4(w4[1], h4[1])
                         + dot4(w4[2], h4[2]) + dot4(w4[3], h4[3]);
                float y1 = dot4(w4[4], h4[4]) + dot4(w4[5], h4[5])
                         + dot4(w4[6], h4[6]) + dot4(w4[7], h4[7]);
                float acc = y0 + y1;
                acc += __shfl_xor_sync(~0u, acc, 1);
                acc += __shfl_xor_sync(~0u, acc, 2);
                acc += __shfl_xor_sync(~0u, acc, 4);
                if (p == 0) {
                    yv[o] = acc;
                    g_outpre[(b * 64 + o) * 256 + n + 1] = acc;
                }
            }
            BARS(5, 512); BARA(2, 1024);              // y ready
            {   // g_0(n+1): z = F0*y + R0 + c_0(n+1)   (ML holds F0)
                const float4* y4 = (const float4*)yv + p * 2;
                float4 x0 = y4[0], x1 = y4[1];
                float a0 = dot4(ML0, x0) + dot4(ML1, x1);
                float a1 = dot4(ML2, x0) + dot4(ML3, x1);
                const float4* m4 = (const float4*)g_M;
                ML0 = m4[mi0]; ML1 = m4[mi0 + 1]; ML2 = m4[mi1]; ML3 = m4[mi1 + 1];
                a0 += __shfl_xor_sync(~0u, a0, 1); a1 += __shfl_xor_sync(~0u, a1, 1);
                a0 += __shfl_xor_sync(~0u, a0, 2); a1 += __shfl_xor_sync(~0u, a1, 2);
                a0 += __shfl_xor_sync(~0u, a0, 4); a1 += __shfl_xor_sync(~0u, a1, 4);
                if (p == 0) {
                    int rb = ((n + 1) & 1) * 128;
                    float z0 = a0 + R0b[rb + o]      + snxt[o];
                    float z1 = a1 + R0b[rb + 64 + o] + snxt[64 + o];
                    gvb[o] = gatefn(z0, z1);
                }
                BARS(5, 512); BARA(10, 1024);         // g_0(n+1) ready (even)
            }
        }
    } else {
        // ===== group B: x, ring, P, R0, skip, cond =====
        const int t = tid - 512;
        const int row = t >> 3, p8 = t & 7;
        const int o2 = t >> 2, q4 = t & 3;
        const int s = t >> 1, q2 = t & 1;
        {
            if (t < 64) xb[t] = 0.f;
            if (t < 128) Pb[128 + t] = 0.f;
            BARS(6, 512); BARA(9, 1024);              // P_1(0) = 0
        }
        for (int n = 0; n < NSTEP; n++) {
#pragma unroll
            for (int j = 1; j < 8; j++) {
                BARS(10 + ((j - 1) & 1), 1024);       // g_{j-1} ready
                {   // x_j = x_{j-1} + Wres_{j-1} g_{j-1};  ring write
                    const float4* w4 = (const float4*)wres + (j - 1) * 1024
                                     + row * 16 + p8 * 2;
                    const float4* g4 = (const float4*)(gvb + (j - 1) * 64) + p8 * 2;
                    float a = dot4(w4[0], g4[0]) + dot4(w4[1], g4[1]);
                    a += __shfl_xor_sync(~0u, a, 1);
                    a += __shfl_xor_sync(~0u, a, 2);
                    a += __shfl_xor_sync(~0u, a, 4);
                    if (p8 == 0) {
                        float v = xb[(j - 1) * 64 + row] + a;
                        xb[j * 64 + row] = v;
                        int slot = c_roff[j] + (n & (c_dil[j] - 1));
                        ring[slot * 64 + row] = v;
                    }
                }
                BARS(6, 512);
                if (j < 7) {   // P_{j+1} = Wz_{j+1} [old_{j+1}; x_j]
                    const float4* w4 = (const float4*)g_wz + (j + 1) * 4096
                                     + o2 * 32 + q4 * 8;
                    int slot = c_roff[j + 1] + (n & (c_dil[j + 1] - 1));
                    const float4* v4 = (q4 < 2)
                        ? (const float4*)(ring + slot * 64) + q4 * 8
                        : (const float4*)(xb + j * 64) + (q4 - 2) * 8;
                    float c0 = dot4(w4[0], v4[0]) + dot4(w4[1], v4[1])
                             + dot4(w4[2], v4[2]) + dot4(w4[3], v4[3]);
                    float c1 = dot4(w4[4], v4[4]) + dot4(w4[5], v4[5])
                             + dot4(w4[6], v4[6]) + dot4(w4[7], v4[7]);
                    float acc = c0 + c1;
                    acc += __shfl_xor_sync(~0u, acc, 1);
                    acc += __shfl_xor_sync(~0u, acc, 2);
                    if (q4 == 0) Pb[(j + 1) * 128 + o2] = acc;
                    BARS(6, 512);
                    BARA(8 + ((j + 1) & 1), 1024);    // P_{j+1} ready
                }
                if (j == 1) {
                    {   // R0(n+1) = Wzo_0 * x_0(n)
                        const float4* w4 = (const float4*)g_wz + o2 * 32 + q4 * 4;
                        const float4* v4 = (const float4*)xb + q4 * 4;
                        float acc = dot4(w4[0], v4[0]) + dot4(w4[1], v4[1])
                                  + dot4(w4[2], v4[2]) + dot4(w4[3], v4[3]);
                        acc += __shfl_xor_sync(~0u, acc, 1);
                        acc += __shfl_xor_sync(~0u, acc, 2);
                        if (q4 == 0) R0b[((n + 1) & 1) * 128 + o2] = acc;
                    }
                    if (n + 1 < NSTEP) {
                        const float* gc = g_cond + ((n + 1) * 2 + b) * 1024;
                        float* sn = sc + ((n + 1) & 1) * 1024;
                        sn[t] = gc[t]; sn[512 + t] = gc[512 + t];
                    }
                }
                {   // skip_{j-1}
                    const float4* w4 = (const float4*)wskip + (j - 1) * 4096
                                     + s * 16 + q2 * 8;
                    const float4* g4 = (const float4*)(gvb + (j - 1) * 64) + q2 * 8;
                    float c0 = dot4(w4[0], g4[0]) + dot4(w4[1], g4[1])
                             + dot4(w4[2], g4[2]) + dot4(w4[3], g4[3]);
                    float c1 = dot4(w4[4], g4[4]) + dot4(w4[5], g4[5])
                             + dot4(w4[6], g4[6]) + dot4(w4[7], g4[7]);
                    float acc = c0 + c1;
                    acc += __shfl_xor_sync(~0u, acc, 1);
                    if (q2 == 0) skipv[s] = (j == 1) ? acc : skipv[s] + acc;
                }
            }
            BARS(11, 1024);                           // g_7 ready (odd)
            {   // skip_7
                const float4* w4 = (const float4*)wskip + 7 * 4096 + s * 16 + q2 * 8;
                const float4* g4 = (const float4*)(gvb + 7 * 64) + q2 * 8;
                float c0 = dot4(w4[0], g4[0]) + dot4(w4[1], g4[1])
                         + dot4(w4[2], g4[2]) + dot4(w4[3], g4[3]);
                float c1 = dot4(w4[4], g4[4]) + dot4(w4[5], g4[5])
                         + dot4(w4[6], g4[6]) + dot4(w4[7], g4[7]);
                float acc = c0 + c1;
                acc += __shfl_xor_sync(~0u, acc, 1);
                if (q2 == 0) skipv[s] += acc;
            }
            BARS(7, 512); BARA(3, 1024);              // skipv ready
            BARS(2, 1024);                            // y ready
            {   // x_0(n+1) = Wembed y(n)
                const float4* w4 = (const float4*)wembed + row * 16 + p8 * 2;
                const float4* y4 = (const float4*)yv + p8 * 2;
                float a = dot4(w4[0], y4[0]) + dot4(w4[1], y4[1]);
                a += __shfl_xor_sync(~0u, a, 1);
                a += __shfl_xor_sync(~0u, a, 2);
                a += __shfl_xor_sync(~0u, a, 4);
                if (p8 == 0) xb[row] = a;
            }
            BARS(6, 512);
            {   // P_1(n+1) = Wz_1 [old_1(n+1); x_0(n+1)]
                const float4* w4 = (const float4*)g_wz + 4096 + o2 * 32 + q4 * 8;
                int slot = c_roff[1] + ((n + 1) & 1);
                const float4* v4 = (q4 < 2)
                    ? (const float4*)(ring + slot * 64) + q4 * 8
                    : (const float4*)xb + (q4 - 2) * 8;
                float c0 = dot4(w4[0], v4[0]) + dot4(w4[1], v4[1])
                         + dot4(w4[2], v4[2]) + dot4(w4[3], v4[3]);
                float c1 = dot4(w4[4], v4[4]) + dot4(w4[5], v4[5])
                         + dot4(w4[6], v4[6]) + dot4(w4[7], v4[7]);
                float acc = c0 + c1;
                acc += __shfl_xor_sync(~0u, acc, 1);
                acc += __shfl_xor_sync(~0u, acc, 2);
                if (q4 == 0) Pb[128 + o2] = acc;
            }
            BARS(6, 512); BARA(9, 1024);              // P_1(n+1) ready
        }
    }
}

extern "C" void kernel_launch(void* const* d_in, const int* in_sizes, int n_in,
                              void* d_out, int out_size) {
    const float* song   = (const float*)d_in[0];
    const float* ds_w   = (const float*)d_in[1];
    const float* ds_g   = (const float*)d_in[2];
    const float* ds_b   = (const float*)d_in[3];
    const float* us_w   = (const float*)d_in[4];
    const float* us_g   = (const float*)d_in[5];
    const float* us_b   = (const float*)d_in[6];
    const float* wembed = (const float*)d_in[7];
    const float* wcond  = (const float*)d_in[8];
    const float* wdil   = (const float*)d_in[9];
    const float* wres   = (const float*)d_in[10];
    const float* wskip  = (const float*)d_in[11];
    const float* wout   = (const float*)d_in[12];
    const float* wend   = (const float*)d_in[13];
    float* out = (float*)d_out;

    cudaFuncSetAttribute(k_loop, cudaFuncAttributeMaxDynamicSharedMemorySize,
                         S_TOT * 4);
    k_downbn<<<64, 256>>>(0, ds_w, song, ds_g, ds_b);
    k_downbn<<<64, 256>>>(1, ds_w + 8192, song, ds_g + 64, ds_b + 64);
    k_prep<<<897, 256>>>(wdil, wcond, wres, wembed);
    k_loop<<<2, 1024, S_TOT * 4>>>(wembed, wres, wskip, wout, wend);
    k_upbn<<<64, 256>>>(0, us_w, us_g, us_b, nullptr);
    k_upbn<<<64, 256>>>(1, us_w + 8192, us_g + 64, us_b + 64, out);
}

// round 15
// speedup vs baseline: 1.1670x; 1.1670x over previous
#include <cuda_runtime.h>
#define NSTEP 255

__device__ float g_W[8 * 128 * 192];
__device__ float g_cond[NSTEP * 2 * 1024];
__device__ float g_ds1[2 * 64 * 512];
__device__ float g_ds2[2 * 64 * 256];
__device__ float g_outpre[2 * 64 * 256];
__device__ float g_up1[2 * 64 * 512];

__device__ __forceinline__ float dot4(float4 a, float4 x) {
    return a.x * x.x + a.y * x.y + a.z * x.z + a.w * x.w;
}
__device__ __forceinline__ float4 relu4(float4 v) {
    v.x = fmaxf(v.x, 0.f); v.y = fmaxf(v.y, 0.f);
    v.z = fmaxf(v.z, 0.f); v.w = fmaxf(v.w, 0.f);
    return v;
}
__device__ __forceinline__ float gatefn(float z0, float z1) {
    float e0 = __expf(2.f * z0), e1 = __expf(-z1);
    return (1.f - __fdividef(2.f, e0 + 1.f)) * __fdividef(1.f, 1.f + e1);
}
#define BARS(id, n) asm volatile("bar.sync %0,%1;" ::"r"(id), "r"(n) : "memory")
#define BARA(id, n) asm volatile("bar.arrive %0,%1;" ::"r"(id), "r"(n) : "memory")

__global__ void k_downbn(int sel, const float* __restrict__ w,
                         const float* __restrict__ song,
                         const float* __restrict__ gamma,
                         const float* __restrict__ beta) {
    int o = blockIdx.x, tid = threadIdx.x;
    int Lout = sel ? 256 : 512;
    const float* in = sel ? g_ds1 : song;
    float* out = sel ? g_ds2 : g_ds1;
    __shared__ float wr[128], rs[256], rq[256];
    if (tid < 128) wr[tid] = w[o * 128 + tid];
    __syncthreads();
    float vals[4];
    int cnt = 2 * Lout / 256;
    float s = 0.f, q = 0.f;
    for (int j = 0; j < cnt; j++) {
        int i = tid + j * 256, bb = i >= Lout, l = i - bb * Lout;
        const float* xin = in + bb * 64 * 2 * Lout;
        float acc = 0.f;
#pragma unroll
        for (int c = 0; c < 64; c++)
            acc += wr[2 * c] * xin[c * 2 * Lout + 2 * l]
                 + wr[2 * c + 1] * xin[c * 2 * Lout + 2 * l + 1];
        vals[j] = acc; s += acc; q += acc * acc;
    }
    rs[tid] = s; rq[tid] = q; __syncthreads();
    for (int st = 128; st; st >>= 1) {
        if (tid < st) { rs[tid] += rs[tid + st]; rq[tid] += rq[tid + st]; }
        __syncthreads();
    }
    float m = rs[0] / (2.f * Lout);
    float inv = rsqrtf(rq[0] / (2.f * Lout) - m * m + 1e-5f);
    float ga = gamma[o], be = beta[o];
    for (int j = 0; j < cnt; j++) {
        int i = tid + j * 256, bb = i >= Lout, l = i - bb * Lout;
        out[(bb * 64 + o) * Lout + l] = fmaxf(ga * (vals[j] - m) * inv + be, 0.f);
    }
}

__global__ void k_upbn(int sel, const float* __restrict__ w,
                       const float* __restrict__ gamma,
                       const float* __restrict__ beta, float* __restrict__ hout) {
    int o = blockIdx.x, tid = threadIdx.x;
    int Lin = sel ? 512 : 256;
    const float* in = sel ? g_up1 : g_outpre;
    float* out = sel ? hout : g_up1;
    __shared__ float wr[128], rs[256], rq[256];
    if (tid < 128) { int i = tid >> 1, k = tid & 1; wr[tid] = w[(i * 64 + o) * 2 + k]; }
    __syncthreads();
    int cnt = 2 * Lin / 256;
    float v0[4], v1[4];
    float s = 0.f, q = 0.f;
    for (int j = 0; j < cnt; j++) {
        int i = tid + j * 256, bb = i >= Lin, l = i - bb * Lin;
        float a0 = 0.f, a1 = 0.f;
#pragma unroll
        for (int c = 0; c < 64; c++) {
            float x = in[(bb * 64 + c) * Lin + l];
            a0 += wr[2 * c] * x; a1 += wr[2 * c + 1] * x;
        }
        v0[j] = a0; v1[j] = a1;
        s += a0 + a1; q += a0 * a0 + a1 * a1;
    }
    rs[tid] = s; rq[tid] = q; __syncthreads();
    for (int st = 128; st; st >>= 1) {
        if (tid < st) { rs[tid] += rs[tid + st]; rq[tid] += rq[tid + st]; }
        __syncthreads();
    }
    float m = rs[0] / (4.f * Lin);
    float inv = rsqrtf(rq[0] / (4.f * Lin) - m * m + 1e-5f);
    float ga = gamma[o], be = beta[o];
    for (int j = 0; j < cnt; j++) {
        int i = tid + j * 256, bb = i >= Lin, l = i - bb * Lin;
        float* op = out + (bb * 64 + o) * 2 * Lin + 2 * l;
        op[0] = fmaxf(ga * (v0[j] - m) * inv + be, 0.f);
        op[1] = fmaxf(ga * (v1[j] - m) * inv + be, 0.f);
    }
}

// prep: cond (0-127), g_W pack (128-895), zero outpre col0 (896)
// g_W[l][row][0:64)=Wzo_l  [64:128)=Wzc_l (l=0: F0=Wzc_0*Wembed)
//          [128:192)=M_{l-1}=Wzc_l*Wres_{l-1} (l=0: 0)
__global__ void k_prep(const float* __restrict__ wdil,
                       const float* __restrict__ wcond,
                       const float* __restrict__ wres,
                       const float* __restrict__ wembed) {
    int bx = blockIdx.x, tid = threadIdx.x;
    if (bx >= 896) {
        if (tid < 128) g_outpre[tid * 256] = 0.f;
        return;
    }
    if (bx >= 128) {
        int idx = (bx - 128) * 256 + tid;
        int l = idx / 24576, rem = idx % 24576;
        int row = rem / 192, c = rem % 192;
        float val;
        if (c < 64) {
            val = wdil[((l * 128 + row) * 64 + c) * 2];
        } else if (c < 128) {
            int k = c - 64;
            if (l == 0) {
                float acc = 0.f;
                for (int r = 0; r < 64; r++)
                    acc += wdil[(row * 64 + r) * 2 + 1] * wembed[r * 64 + k];
                val = acc;
            } else val = wdil[((l * 128 + row) * 64 + k) * 2 + 1];
        } else {
            int k = c - 128;
            if (l == 0) val = 0.f;
            else {
                float acc = 0.f;
                for (int r = 0; r < 64; r++)
                    acc += wdil[((l * 128 + row) * 64 + r) * 2 + 1]
                         * wres[(l - 1) * 4096 + r * 64 + k];
                val = acc;
            }
        }
        g_W[idx] = val;
        return;
    }
    __shared__ __align__(16) float wt[128 * 64];
    __shared__ __align__(16) float col[128];
    int ob = (bx & 7) * 128, gy = bx >> 3;
    for (int i = tid; i < 128 * 64; i += 256) wt[i] = wcond[ob * 64 + i];
    for (int nn = 0; nn < 16; nn++) {
        int n = gy * 16 + nn;
        if (n >= NSTEP) break;
        __syncthreads();
        if (tid < 128) {
            int b = tid >> 6, c = tid & 63;
            col[tid] = g_ds2[(b * 64 + c) * 256 + n];
        }
        __syncthreads();
        int oo = tid >> 1, b = tid & 1;
        const float4* w4 = (const float4*)(wt + oo * 64);
        const float4* c4 = (const float4*)(col + b * 64);
        float acc = 0.f;
#pragma unroll
        for (int j = 0; j < 16; j++) acc += dot4(w4[j], c4[j]);
        g_cond[(n * 2 + b) * 1024 + ob + oo] = acc;
    }
}

#define S_RING 0
#define S_SC   16320
#define S_GVB  18368
#define S_XB   18880
#define S_SKIP 19392
#define S_H2   19648
#define S_YV   19904
#define S_TOT  19968

__constant__ int c_dil[8]  = {1, 2, 4, 8, 16, 32, 64, 128};
__constant__ int c_roff[8] = {0, 1, 3, 7, 15, 31, 63, 127};

__global__ void __launch_bounds__(1024, 1)
k_loop(const float* __restrict__ wembed, const float* __restrict__ wres,
       const float* __restrict__ wskip, const float* __restrict__ wout,
       const float* __restrict__ wend) {
    extern __shared__ float sm[];
    float* ring  = sm + S_RING;
    float* sc    = sm + S_SC;
    float* gvb   = sm + S_GVB;
    float* xb    = sm + S_XB;
    float* skipv = sm + S_SKIP;
    float* h2    = sm + S_H2;
    float* yv    = sm + S_YV;
    const int b = blockIdx.x, tid = threadIdx.x;

    for (int i = tid; i < 16320; i += 1024) ring[i] = 0.f;
    sc[tid] = g_cond[b * 1024 + tid];
    if (tid < 64) yv[tid] = 0.f;
    if (tid < 512) xb[tid] = 0.f;
    __syncthreads();

    if (tid < 512) {
        // ===== group A: one fused 192-in matvec + gate per layer =====
        const int w = tid >> 5, lane = tid & 31;
        const int sub = lane >> 2, q = lane & 3;
        const bool hi = sub >= 4;
        const int ro = w * 4 + (sub & 3) + (hi ? 64 : 0);    // my output row
        const float4* gW4 = (const float4*)g_W;
        for (int n = 0; n < NSTEP; n++) {
            const float* scur = sc + (n & 1) * 1024;
#pragma unroll
            for (int l = 0; l < 8; l++) {
                const float4* Wr = gW4 + (l * 128 + ro) * 48;
                float4 W0 = Wr[4 * q], W1 = Wr[4 * q + 1],
                       W2 = Wr[4 * q + 2], W3 = Wr[4 * q + 3];
                const int slot = c_roff[l] + (n & (c_dil[l] - 1));
                const float4* vo = (const float4*)(ring + slot * 64) + 4 * q;
                float a = dot4(W0, vo[0]) + dot4(W1, vo[1])
                        + dot4(W2, vo[2]) + dot4(W3, vo[3]);
                float4 X0 = Wr[16 + 4 * q], X1 = Wr[17 + 4 * q],
                       X2 = Wr[18 + 4 * q], X3 = Wr[19 + 4 * q];
                float4 G0 = Wr[32 + 4 * q], G1 = Wr[33 + 4 * q],
                       G2 = Wr[34 + 4 * q], G3 = Wr[35 + 4 * q];
                if (l) BARS(8 + ((l - 1) & 1), 1024);     // x_{l-1} ready
                const float4* vx = (l ? (const float4*)(xb + (l - 1) * 64)
                                      : (const float4*)yv) + 4 * q;
                const float4* vg = (l ? (const float4*)(gvb + (l - 1) * 64)
                                      : (const float4*)yv) + 4 * q;
                float ax = dot4(X0, vx[0]) + dot4(X1, vx[1])
                         + dot4(X2, vx[2]) + dot4(X3, vx[3]);
                float ag = dot4(G0, vg[0]) + dot4(G1, vg[1])
                         + dot4(G2, vg[2]) + dot4(G3, vg[3]);
                a += ax + ag;
                a += __shfl_xor_sync(~0u, a, 1);
                a += __shfl_xor_sync(~0u, a, 2);
                float zo = a + scur[l * 128 + ro];
                float zp = __shfl_xor_sync(~0u, zo, 16);  // partner row ro^64
                if (!hi && q == 0) gvb[l * 64 + ro] = gatefn(zo, zp);
                BARS(5, 512); BARA(10 + (l & 1), 1024);   // g_l ready
            }
            BARS(3, 1024);                                // skipv ready
            {   // h2 = relu(wout @ relu(skipv))
                int o2 = tid >> 1, qq = tid & 1;
                const float4* w4 = (const float4*)wout + o2 * 64 + qq * 32;
                const float4* v4 = (const float4*)skipv + qq * 32;
                float c0 = 0.f, c1 = 0.f, c2 = 0.f, c3 = 0.f;
#pragma unroll
                for (int j = 0; j < 8; j++) {
                    c0 += dot4(w4[4 * j],     relu4(v4[4 * j]));
                    c1 += dot4(w4[4 * j + 1], relu4(v4[4 * j + 1]));
                    c2 += dot4(w4[4 * j + 2], relu4(v4[4 * j + 2]));
                    c3 += dot4(w4[4 * j + 3], relu4(v4[4 * j + 3]));
                }
                float acc = (c0 + c1) + (c2 + c3);
                acc += __shfl_xor_sync(~0u, acc, 1);
                if (qq == 0) h2[o2] = fmaxf(acc, 0.f);
            }
            BARS(4, 512);
            {   // y = wend @ h2
                int o = tid >> 3, p = tid & 7;
                const float4* w4 = (const float4*)wend + o * 64 + p * 8;
                const float4* h4 = (const float4*)h2 + p * 8;
                float y0 = dot4(w4[0], h4[0]) + dot4(w4[1], h4[1])
                         + dot4(w4[2], h4[2]) + dot4(w4[3], h4[3]);
                float y1 = dot4(w4[4], h4[4]) + dot4(w4[5], h4[5])
                         + dot4(w4[6], h4[6]) + dot4(w4[7], h4[7]);
                float acc = y0 + y1;
                acc += __shfl_xor_sync(~0u, acc, 1);
                acc += __shfl_xor_sync(~0u, acc, 2);
                acc += __shfl_xor_sync(~0u, acc, 4);
                if (p == 0) {
                    yv[o] = acc;
                    g_outpre[(b * 64 + o) * 256 + n + 1] = acc;
                }
            }
            BARS(5, 512); BARA(2, 1024);                  // y ready
        }
    } else {
        // ===== group B: x chain, ring, skip, cond =====
        const int t = tid - 512;
        const int row8 = t >> 3, p8 = t & 7;
        const int s = t >> 1, q2 = t & 1;
        BARA(8, 1024);                                    // x_0(0)=0 ready
        for (int n = 0; n < NSTEP; n++) {
#pragma unroll
            for (int j = 0; j < 7; j++) {
                BARS(10 + (j & 1), 1024);                 // g_j ready
                if (t < 64)
                    ring[(c_roff[j] + (n & (c_dil[j] - 1))) * 64 + t] = xb[j * 64 + t];
                {   // x_{j+1} = x_j + Wres_j g_j
                    const float4* w4 = (const float4*)wres + j * 1024
                                     + row8 * 16 + p8 * 2;
                    const float4* g4 = (const float4*)(gvb + j * 64) + p8 * 2;
                    float a = dot4(w4[0], g4[0]) + dot4(w4[1], g4[1]);
                    a += __shfl_xor_sync(~0u, a, 1);
                    a += __shfl_xor_sync(~0u, a, 2);
                    a += __shfl_xor_sync(~0u, a, 4);
                    if (p8 == 0)
                        xb[(j + 1) * 64 + row8] = xb[j * 64 + row8] + a;
                }
                BARS(6, 512);
                if (j < 6) BARA(8 + ((j + 1) & 1), 1024); // x_{j+1} ready (x_7: no consumer)
                {   // skip_j (off-path)  [FIX: layer stride 4096 float4s]
                    const float4* w4 = (const float4*)wskip + j * 4096
                                     + s * 16 + q2 * 8;
                    const float4* g4 = (const float4*)(gvb + j * 64) + q2 * 8;
                    float c0 = dot4(w4[0], g4[0]) + dot4(w4[1], g4[1])
                             + dot4(w4[2], g4[2]) + dot4(w4[3], g4[3]);
                    float c1 = dot4(w4[4], g4[4]) + dot4(w4[5], g4[5])
                             + dot4(w4[6], g4[6]) + dot4(w4[7], g4[7]);
                    float acc = c0 + c1;
                    acc += __shfl_xor_sync(~0u, acc, 1);
                    if (q2 == 0) skipv[s] = j ? skipv[s] + acc : acc;
                }
                if (j == 0 && n + 1 < NSTEP) {            // cond prefetch
                    const float* gc = g_cond + ((n + 1) * 2 + b) * 1024;
                    float* sn = sc + ((n + 1) & 1) * 1024;
                    sn[t] = gc[t]; sn[512 + t] = gc[512 + t];
                }
            }
            BARS(11, 1024);                               // g_7 ready
            if (t < 64) ring[(127 + (n & 127)) * 64 + t] = xb[7 * 64 + t];
            {   // skip_7  [FIX: 7*4096]
                const float4* w4 = (const float4*)wskip + 7 * 4096 + s * 16 + q2 * 8;
                const float4* g4 = (const float4*)(gvb + 7 * 64) + q2 * 8;
                float c0 = dot4(w4[0], g4[0]) + dot4(w4[1], g4[1])
                         + dot4(w4[2], g4[2]) + dot4(w4[3], g4[3]);
                float c1 = dot4(w4[4], g4[4]) + dot4(w4[5], g4[5])
                         + dot4(w4[6], g4[6]) + dot4(w4[7], g4[7]);
                float acc = c0 + c1;
                acc += __shfl_xor_sync(~0u, acc, 1);
                if (q2 == 0) skipv[s] += acc;
            }
            BARS(7, 512);
            BARA(3, 1024);                                // skipv ready
            BARS(2, 1024);                                // y ready
            {   // x_0(next) = Wembed y
                const float4* w4 = (const float4*)wembed + row8 * 16 + p8 * 2;
                const float4* y4 = (const float4*)yv + p8 * 2;
                float a = dot4(w4[0], y4[0]) + dot4(w4[1], y4[1]);
                a += __shfl_xor_sync(~0u, a, 1);
                a += __shfl_xor_sync(~0u, a, 2);
                a += __shfl_xor_sync(~0u, a, 4);
                if (p8 == 0) xb[row8] = a;
            }
            BARS(6, 512);
            BARA(8, 1024);                                // x_0 ready
        }
    }
}

extern "C" void kernel_launch(void* const* d_in, const int* in_sizes, int n_in,
                              void* d_out, int out_size) {
    const float* song   = (const float*)d_in[0];
    const float* ds_w   = (const float*)d_in[1];
    const float* ds_g   = (const float*)d_in[2];
    const float* ds_b   = (const float*)d_in[3];
    const float* us_w   = (const float*)d_in[4];
    const float* us_g   = (const float*)d_in[5];
    const float* us_b   = (const float*)d_in[6];
    const float* wembed = (const float*)d_in[7];
    const float* wcond  = (const float*)d_in[8];
    const float* wdil   = (const float*)d_in[9];
    const float* wres   = (const float*)d_in[10];
    const float* wskip  = (const float*)d_in[11];
    const float* wout   = (const float*)d_in[12];
    const float* wend   = (const float*)d_in[13];
    float* out = (float*)d_out;

    cudaFuncSetAttribute(k_loop, cudaFuncAttributeMaxDynamicSharedMemorySize,
                         S_TOT * 4);
    k_downbn<<<64, 256>>>(0, ds_w, song, ds_g, ds_b);
    k_downbn<<<64, 256>>>(1, ds_w + 8192, song, ds_g + 64, ds_b + 64);
    k_prep<<<897, 256>>>(wdil, wcond, wres, wembed);
    k_loop<<<2, 1024, S_TOT * 4>>>(wembed, wres, wskip, wout, wend);
    k_upbn<<<64, 256>>>(0, us_w, us_g, us_b, nullptr);
    k_upbn<<<64, 256>>>(1, us_w + 8192, us_g + 64, us_b + 64, out);
}